// round 7
// baseline (speedup 1.0000x reference)
#include <cuda_runtime.h>
#include <cuda_bf16.h>

#define TT 512
#define MM 16
#define MH 8
#define PP 600
#define BB 32
#define CH 256        // K-chunk length (typical K ~88 -> single chunk)

typedef unsigned long long ull;

__device__ __forceinline__ float ex2(float v) {
    float r;
    asm("ex2.approx.ftz.f32 %0, %1;" : "=f"(r) : "f"(v));
    return r;
}
__device__ __forceinline__ ull pack2(float lo, float hi) {
    ull r;
    asm("mov.b64 %0, {%1, %2};" : "=l"(r) : "f"(lo), "f"(hi));
    return r;
}
__device__ __forceinline__ void unpack2(ull v, float& lo, float& hi) {
    asm("mov.b64 {%0, %1}, %2;" : "=f"(lo), "=f"(hi) : "l"(v));
}
__device__ __forceinline__ ull fma2(ull a, ull b, ull c) {
    ull d;
    asm("fma.rn.f32x2 %0, %1, %2, %3;" : "=l"(d) : "l"(a), "l"(b), "l"(c));
    return d;
}

// smem (floats):
//   [0, 512)       sxc : compacted scaled x (+ sentinels)
//   [512, 1024)    sidx: compacted t index (int)
//   [1024, 5120)   skyc: float2[MH][CH] chunk of (k,y); overlaid as scr
//   [5120, 5124)   swsum[4]
// total 5128 floats = 20.5 KB; 8 blocks/SM (reg-bound at 64 regs).

template<bool EQ>
__device__ __forceinline__ void chunk_mma(
    const float* sxc, const float2* skyc, int c0, int cend, int tq,
    float v0, float v1, float r0, float r1,
    ull* __restrict__ accA, ull* __restrict__ accB)
{
    for (int jj = c0 + 2 * tq; jj < cend; jj += 8) {
        float2 xv = *(const float2*)(sxc + jj);        // LDS.64 broadcast
        float dA0 = v0 - xv.x, dA1 = v0 - xv.y;
        float dB0 = v1 - xv.x, dB1 = v1 - xv.y;
        float eA0 = dA0 * (-dA0), eA1 = dA1 * (-dA1);
        float eB0 = dB0 * (-dB0), eB1 = dB1 * (-dB1);

        ull wA0, wA1, wB0, wB1;
        if (EQ) {
            float w;
            w = ex2(eA0); wA0 = pack2(w, w);
            w = ex2(eA1); wA1 = pack2(w, w);
            w = ex2(eB0); wB0 = pack2(w, w);
            w = ex2(eB1); wB1 = pack2(w, w);
        } else {
            wA0 = pack2(ex2(eA0 * r0), ex2(eA0 * r1));
            wA1 = pack2(ex2(eA1 * r0), ex2(eA1 * r1));
            wB0 = pack2(ex2(eB0 * r0), ex2(eB0 * r1));
            wB1 = pack2(ex2(eB1 * r0), ex2(eB1 * r1));
        }

        const int jl = jj - c0;
        #pragma unroll
        for (int m = 0; m < MH; m++) {
            ulonglong2 q = *(const ulonglong2*)(skyc + m * CH + jl); // LDS.128
            accA[m] = fma2(q.y, wA1, fma2(q.x, wA0, accA[m]));
            accB[m] = fma2(q.y, wB1, fma2(q.x, wB0, accB[m]));
        }
    }
}

__global__ __launch_bounds__(128, 8) void func_repr_kernel(
    const float* __restrict__ y, const float* __restrict__ x,
    const int*   __restrict__ mask, const float* __restrict__ sigma,
    float* __restrict__ out)
{
    extern __shared__ float sm[];
    float*  sxc   = sm;
    int*    sidx  = (int*)(sm + 512);
    float2* skyc  = (float2*)(sm + 1024);
    int*    swsum = (int*)(sm + 5120);

    const int b    = blockIdx.y;
    const int h    = blockIdx.z;
    const int tid  = threadIdx.x;
    const int lane = tid & 31;
    const int wrp  = tid >> 5;
    const int pl   = lane;
    const int tq   = wrp;

    const float s0 = sigma[0], s1 = sigma[1];
    const float LOG2E = 1.4426950408889634f;
    const float smax  = fmaxf(s0, s1);
    const float rcmin = sqrtf(0.5f * LOG2E) / smax;     // sqrt(c_min)
    const float r0 = (smax / s0) * (smax / s0);
    const float r1 = (smax / s1) * (smax / s1);

    const int   pfirst = blockIdx.x * 64;
    const float gA = fmaf((float)pfirst,        50.0f / 599.0f, -1.0f);
    const float gZ = fmaf((float)(pfirst + 63), 50.0f / 599.0f, -1.0f);
    const float vlo = rcmin * gA - 6.7f;   // 6.7^2=44.9 -> dropped weight <= 3e-14
    const float vhi = rcmin * gZ + 6.7f;

    // ---- deterministic compaction of x into [vlo, vhi] ----
    float4 xv4 = ((const float4*)(x + (size_t)b * TT))[tid];  // t = 4*tid..+3
    float vv[4] = { xv4.x * rcmin, xv4.y * rcmin, xv4.z * rcmin, xv4.w * rcmin };
    int pass = 0, cnt = 0;
    #pragma unroll
    for (int k = 0; k < 4; k++) {
        bool in = (vv[k] >= vlo) & (vv[k] <= vhi);
        pass |= (int)in << k;
        cnt  += (int)in;
    }
    int incl = cnt;
    #pragma unroll
    for (int o = 1; o < 32; o <<= 1) {
        int n = __shfl_up_sync(0xFFFFFFFFu, incl, o);
        if (lane >= o) incl += n;
    }
    if (lane == 31) swsum[wrp] = incl;
    __syncthreads();

    int w0 = swsum[0], w1 = swsum[1], w2 = swsum[2], w3 = swsum[3];
    int woff = (wrp > 0 ? w0 : 0) + (wrp > 1 ? w1 : 0) + (wrp > 2 ? w2 : 0);
    const int K  = w0 + w1 + w2 + w3;
    const int Kp = (K + 7) & ~7;

    {
        int pos = woff + incl - cnt;
        #pragma unroll
        for (int k = 0; k < 4; k++) {
            if ((pass >> k) & 1) {
                sxc[pos]  = vv[k];
                sidx[pos] = tid * 4 + k;
                pos++;
            }
        }
    }
    if (tid < Kp - K) sxc[K + tid] = 1.0e9f;   // sentinel -> weight 0
    __syncthreads();

    const int p0 = pfirst + pl;
    const int p1 = p0 + 32;
    const float v0 = rcmin * fmaf((float)p0, 50.0f / 599.0f, -1.0f);
    const float v1 = rcmin * fmaf((float)p1, 50.0f / 599.0f, -1.0f);

    ull accA[MH], accB[MH];
    #pragma unroll
    for (int m = 0; m < MH; m++) { accA[m] = 0ULL; accB[m] = 0ULL; }

    const float* yb = y    + ((size_t)b * MM + h * MH) * TT;
    const int*   mb = mask + ((size_t)b * MM + h * MH) * TT;

    // ---- chunked gather + MMA (typical K<=256: one iteration) ----
    for (int c0 = 0; c0 < Kp; c0 += CH) {
        const int cend = min(c0 + CH, Kp);

        // coalesced gather: warp-per-row, lanes take consecutive j
        #pragma unroll
        for (int m = wrp; m < MH; m += 4) {
            const int*   mrow = mb + m * TT;
            const float* yrow = yb + m * TT;
            for (int j = c0 + lane; j < cend; j += 32) {
                float2 kv;
                if (j < K) {
                    int t = sidx[j];
                    kv = make_float2((float)__ldg(mrow + t), __ldg(yrow + t));
                } else {
                    kv = make_float2(0.f, 0.f);
                }
                skyc[m * CH + (j - c0)] = kv;
            }
        }
        __syncthreads();

        if (s0 == s1)
            chunk_mma<true >(sxc, skyc, c0, cend, tq, v0, v1, r0, r1, accA, accB);
        else
            chunk_mma<false>(sxc, skyc, c0, cend, tq, v0, v1, r0, r1, accA, accB);
        __syncthreads();   // before next chunk overwrites skyc / scr overlay
    }

    // ---- cross-quarter reduction (scratch overlays skyc) ----
    float* scr = sm + 1024;           // 3 * 32 * 33 = 3168 <= 4096 floats
    if (tq > 0) {
        float* s = scr + ((tq - 1) * 32 + pl) * 33;
        #pragma unroll
        for (int m = 0; m < MH; m++) {
            float lo, hi;
            unpack2(accA[m], lo, hi);
            s[2 * m] = lo; s[2 * m + 1] = hi;
            unpack2(accB[m], lo, hi);
            s[16 + 2 * m] = lo; s[16 + 2 * m + 1] = hi;
        }
    }
    __syncthreads();

    if (tq == 0) {
        const float* q1 = scr + (0 * 32 + pl) * 33;
        const float* q2 = scr + (1 * 32 + pl) * 33;
        const float* q3 = scr + (2 * 32 + pl) * 33;

        if (p0 < PP) {
            float4* op = (float4*)(out + ((size_t)b * PP + p0) * (2 * MM) + h * 2 * MH);
            #pragma unroll
            for (int m = 0; m < MH; m += 2) {
                float dA, cA, dB, cB;
                unpack2(accA[m],     dA, cA);
                unpack2(accA[m + 1], dB, cB);
                dA += q1[2*m]   + q2[2*m]   + q3[2*m];
                cA += q1[2*m+1] + q2[2*m+1] + q3[2*m+1];
                dB += q1[2*m+2] + q2[2*m+2] + q3[2*m+2];
                cB += q1[2*m+3] + q2[2*m+3] + q3[2*m+3];
                op[m >> 1] = make_float4(dA, __fdividef(cA, dA + 1e-8f),
                                         dB, __fdividef(cB, dB + 1e-8f));
            }
        }
        if (p1 < PP) {
            float4* op = (float4*)(out + ((size_t)b * PP + p1) * (2 * MM) + h * 2 * MH);
            #pragma unroll
            for (int m = 0; m < MH; m += 2) {
                float dA, cA, dB, cB;
                unpack2(accB[m],     dA, cA);
                unpack2(accB[m + 1], dB, cB);
                dA += q1[16+2*m]   + q2[16+2*m]   + q3[16+2*m];
                cA += q1[16+2*m+1] + q2[16+2*m+1] + q3[16+2*m+1];
                dB += q1[16+2*m+2] + q2[16+2*m+2] + q3[16+2*m+2];
                cB += q1[16+2*m+3] + q2[16+2*m+3] + q3[16+2*m+3];
                op[m >> 1] = make_float4(dA, __fdividef(cA, dA + 1e-8f),
                                         dB, __fdividef(cB, dB + 1e-8f));
            }
        }
    }
}

extern "C" void kernel_launch(void* const* d_in, const int* in_sizes, int n_in,
                              void* d_out, int out_size) {
    const float* y     = (const float*)d_in[0];
    const float* x     = (const float*)d_in[1];
    const int*   mask  = (const int*)  d_in[2];
    const float* sigma = (const float*)d_in[3];
    float*       out   = (float*)d_out;

    const size_t smem = 5128 * sizeof(float);   // 20.5 KB
    cudaFuncSetAttribute(func_repr_kernel,
                         cudaFuncAttributeMaxDynamicSharedMemorySize, (int)smem);

    dim3 grid((PP + 63) / 64, BB, 2);
    func_repr_kernel<<<grid, 128, smem>>>(y, x, mask, sigma, out);
}

// round 8
// speedup vs baseline: 1.0147x; 1.0147x over previous
#include <cuda_runtime.h>
#include <cuda_bf16.h>

#define TT 512
#define MM 16
#define MH 4          // m rows per block (quarter)
#define PP 600
#define BB 32
#define CH 256        // K-chunk length (typical K ~80 -> single chunk)

typedef unsigned long long ull;

__device__ __forceinline__ float ex2(float v) {
    float r;
    asm("ex2.approx.ftz.f32 %0, %1;" : "=f"(r) : "f"(v));
    return r;
}
__device__ __forceinline__ ull pack2(float lo, float hi) {
    ull r;
    asm("mov.b64 %0, {%1, %2};" : "=l"(r) : "f"(lo), "f"(hi));
    return r;
}
__device__ __forceinline__ void unpack2(ull v, float& lo, float& hi) {
    asm("mov.b64 {%0, %1}, %2;" : "=f"(lo), "=f"(hi) : "l"(v));
}
__device__ __forceinline__ ull fma2(ull a, ull b, ull c) {
    ull d;
    asm("fma.rn.f32x2 %0, %1, %2, %3;" : "=l"(d) : "l"(a), "l"(b), "l"(c));
    return d;
}

// smem (floats):
//   [0, 512)       sxc : compacted scaled x (+ sentinels)
//   [512, 1024)    sidx: compacted t index (int)
//   [1024, 3072)   skyc: float2[MH][CH] chunk of (k,y); overlaid as scr
//   [3072, 3076)   swsum[4]
// total 3076 floats = 12.3 KB; grid 1280 blocks -> ~8 resident/SM (reg-bound).

template<bool EQ>
__device__ __forceinline__ void chunk_mma(
    const float* sxc, const float2* skyc, int c0, int cend, int tq,
    float v0, float v1, float r0, float r1,
    ull* __restrict__ accA, ull* __restrict__ accB)
{
    for (int jj = c0 + 2 * tq; jj < cend; jj += 8) {
        float2 xv = *(const float2*)(sxc + jj);        // LDS.64 broadcast
        float dA0 = v0 - xv.x, dA1 = v0 - xv.y;
        float dB0 = v1 - xv.x, dB1 = v1 - xv.y;
        float eA0 = dA0 * (-dA0), eA1 = dA1 * (-dA1);
        float eB0 = dB0 * (-dB0), eB1 = dB1 * (-dB1);

        ull wA0, wA1, wB0, wB1;
        if (EQ) {
            float w;
            w = ex2(eA0); wA0 = pack2(w, w);
            w = ex2(eA1); wA1 = pack2(w, w);
            w = ex2(eB0); wB0 = pack2(w, w);
            w = ex2(eB1); wB1 = pack2(w, w);
        } else {
            wA0 = pack2(ex2(eA0 * r0), ex2(eA0 * r1));
            wA1 = pack2(ex2(eA1 * r0), ex2(eA1 * r1));
            wB0 = pack2(ex2(eB0 * r0), ex2(eB0 * r1));
            wB1 = pack2(ex2(eB1 * r0), ex2(eB1 * r1));
        }

        const int jl = jj - c0;
        #pragma unroll
        for (int m = 0; m < MH; m++) {
            ulonglong2 q = *(const ulonglong2*)(skyc + m * CH + jl); // LDS.128
            accA[m] = fma2(q.y, wA1, fma2(q.x, wA0, accA[m]));
            accB[m] = fma2(q.y, wB1, fma2(q.x, wB0, accB[m]));
        }
    }
}

__global__ __launch_bounds__(128, 8) void func_repr_kernel(
    const float* __restrict__ y, const float* __restrict__ x,
    const int*   __restrict__ mask, const float* __restrict__ sigma,
    float* __restrict__ out)
{
    extern __shared__ float sm[];
    float*  sxc   = sm;
    int*    sidx  = (int*)(sm + 512);
    float2* skyc  = (float2*)(sm + 1024);
    int*    swsum = (int*)(sm + 3072);

    const int b    = blockIdx.y;
    const int h    = blockIdx.z;                 // m-quarter 0..3
    const int tid  = threadIdx.x;
    const int lane = tid & 31;
    const int wrp  = tid >> 5;
    const int pl   = lane;
    const int tq   = wrp;

    const float s0 = sigma[0], s1 = sigma[1];
    const float LOG2E = 1.4426950408889634f;
    const float smax  = fmaxf(s0, s1);
    const float rcmin = sqrtf(0.5f * LOG2E) / smax;     // sqrt(c_min)
    const float r0 = (smax / s0) * (smax / s0);
    const float r1 = (smax / s1) * (smax / s1);

    const int   pfirst = blockIdx.x * 64;
    const float gA = fmaf((float)pfirst,        50.0f / 599.0f, -1.0f);
    const float gZ = fmaf((float)(pfirst + 63), 50.0f / 599.0f, -1.0f);
    const float vlo = rcmin * gA - 6.7f;   // 6.7^2=44.9 -> dropped weight <= 3e-14
    const float vhi = rcmin * gZ + 6.7f;

    // ---- deterministic compaction of x into [vlo, vhi] ----
    float4 xv4 = ((const float4*)(x + (size_t)b * TT))[tid];  // t = 4*tid..+3
    float vv[4] = { xv4.x * rcmin, xv4.y * rcmin, xv4.z * rcmin, xv4.w * rcmin };
    int pass = 0, cnt = 0;
    #pragma unroll
    for (int k = 0; k < 4; k++) {
        bool in = (vv[k] >= vlo) & (vv[k] <= vhi);
        pass |= (int)in << k;
        cnt  += (int)in;
    }
    int incl = cnt;
    #pragma unroll
    for (int o = 1; o < 32; o <<= 1) {
        int n = __shfl_up_sync(0xFFFFFFFFu, incl, o);
        if (lane >= o) incl += n;
    }
    if (lane == 31) swsum[wrp] = incl;
    __syncthreads();

    int w0 = swsum[0], w1 = swsum[1], w2 = swsum[2], w3 = swsum[3];
    int woff = (wrp > 0 ? w0 : 0) + (wrp > 1 ? w1 : 0) + (wrp > 2 ? w2 : 0);
    const int K  = w0 + w1 + w2 + w3;
    const int Kp = (K + 7) & ~7;

    {
        int pos = woff + incl - cnt;
        #pragma unroll
        for (int k = 0; k < 4; k++) {
            if ((pass >> k) & 1) {
                sxc[pos]  = vv[k];
                sidx[pos] = tid * 4 + k;
                pos++;
            }
        }
    }
    if (tid < Kp - K) sxc[K + tid] = 1.0e9f;   // sentinel -> weight 0
    __syncthreads();

    const int p0 = pfirst + pl;
    const int p1 = p0 + 32;
    const float v0 = rcmin * fmaf((float)p0, 50.0f / 599.0f, -1.0f);
    const float v1 = rcmin * fmaf((float)p1, 50.0f / 599.0f, -1.0f);

    ull accA[MH], accB[MH];
    #pragma unroll
    for (int m = 0; m < MH; m++) { accA[m] = 0ULL; accB[m] = 0ULL; }

    const float* yb = y    + ((size_t)b * MM + h * MH) * TT;
    const int*   mb = mask + ((size_t)b * MM + h * MH) * TT;

    // ---- chunked gather + MMA (typical K<=256: one iteration) ----
    for (int c0 = 0; c0 < Kp; c0 += CH) {
        const int cend = min(c0 + CH, Kp);

        // coalesced gather: warp-per-row, lanes take consecutive j
        #pragma unroll
        for (int m = wrp; m < MH; m += 4) {
            const int*   mrow = mb + m * TT;
            const float* yrow = yb + m * TT;
            for (int j = c0 + lane; j < cend; j += 32) {
                float2 kv;
                if (j < K) {
                    int t = sidx[j];
                    kv = make_float2((float)__ldg(mrow + t), __ldg(yrow + t));
                } else {
                    kv = make_float2(0.f, 0.f);
                }
                skyc[m * CH + (j - c0)] = kv;
            }
        }
        __syncthreads();

        if (s0 == s1)
            chunk_mma<true >(sxc, skyc, c0, cend, tq, v0, v1, r0, r1, accA, accB);
        else
            chunk_mma<false>(sxc, skyc, c0, cend, tq, v0, v1, r0, r1, accA, accB);
        __syncthreads();   // before next chunk / scr overlay
    }

    // ---- cross-quarter reduction (scratch overlays skyc) ----
    float* scr = sm + 1024;           // 3 * 32 * 17 = 1632 <= 2048 floats
    if (tq > 0) {
        float* s = scr + ((tq - 1) * 32 + pl) * 17;
        #pragma unroll
        for (int m = 0; m < MH; m++) {
            float lo, hi;
            unpack2(accA[m], lo, hi);
            s[2 * m] = lo; s[2 * m + 1] = hi;
            unpack2(accB[m], lo, hi);
            s[8 + 2 * m] = lo; s[8 + 2 * m + 1] = hi;
        }
    }
    __syncthreads();

    if (tq == 0) {
        const float* q1 = scr + (0 * 32 + pl) * 17;
        const float* q2 = scr + (1 * 32 + pl) * 17;
        const float* q3 = scr + (2 * 32 + pl) * 17;

        if (p0 < PP) {
            float4* op = (float4*)(out + ((size_t)b * PP + p0) * (2 * MM) + h * 2 * MH);
            #pragma unroll
            for (int m = 0; m < MH; m += 2) {
                float dA, cA, dB, cB;
                unpack2(accA[m],     dA, cA);
                unpack2(accA[m + 1], dB, cB);
                dA += q1[2*m]   + q2[2*m]   + q3[2*m];
                cA += q1[2*m+1] + q2[2*m+1] + q3[2*m+1];
                dB += q1[2*m+2] + q2[2*m+2] + q3[2*m+2];
                cB += q1[2*m+3] + q2[2*m+3] + q3[2*m+3];
                op[m >> 1] = make_float4(dA, __fdividef(cA, dA + 1e-8f),
                                         dB, __fdividef(cB, dB + 1e-8f));
            }
        }
        if (p1 < PP) {
            float4* op = (float4*)(out + ((size_t)b * PP + p1) * (2 * MM) + h * 2 * MH);
            #pragma unroll
            for (int m = 0; m < MH; m += 2) {
                float dA, cA, dB, cB;
                unpack2(accB[m],     dA, cA);
                unpack2(accB[m + 1], dB, cB);
                dA += q1[8+2*m]   + q2[8+2*m]   + q3[8+2*m];
                cA += q1[8+2*m+1] + q2[8+2*m+1] + q3[8+2*m+1];
                dB += q1[8+2*m+2] + q2[8+2*m+2] + q3[8+2*m+2];
                cB += q1[8+2*m+3] + q2[8+2*m+3] + q3[8+2*m+3];
                op[m >> 1] = make_float4(dA, __fdividef(cA, dA + 1e-8f),
                                         dB, __fdividef(cB, dB + 1e-8f));
            }
        }
    }
}

extern "C" void kernel_launch(void* const* d_in, const int* in_sizes, int n_in,
                              void* d_out, int out_size) {
    const float* y     = (const float*)d_in[0];
    const float* x     = (const float*)d_in[1];
    const int*   mask  = (const int*)  d_in[2];
    const float* sigma = (const float*)d_in[3];
    float*       out   = (float*)d_out;

    const size_t smem = 3076 * sizeof(float);   // 12.3 KB
    cudaFuncSetAttribute(func_repr_kernel,
                         cudaFuncAttributeMaxDynamicSharedMemorySize, (int)smem);

    dim3 grid((PP + 63) / 64, BB, 4);
    func_repr_kernel<<<grid, 128, smem>>>(y, x, mask, sigma, out);
}

// round 9
// speedup vs baseline: 1.0198x; 1.0049x over previous
#include <cuda_runtime.h>
#include <cuda_bf16.h>

#define TT 512
#define MM 16
#define PP 600
#define BB 32
#define PW 32         // p-tile width
#define NPT 19        // ceil(600/32)
#define CH 256        // K-chunk length (typical K ~56 -> single chunk)

typedef unsigned long long ull;

__device__ __forceinline__ float ex2(float v) {
    float r;
    asm("ex2.approx.ftz.f32 %0, %1;" : "=f"(r) : "f"(v));
    return r;
}
__device__ __forceinline__ ull pack2(float lo, float hi) {
    ull r;
    asm("mov.b64 %0, {%1, %2};" : "=l"(r) : "f"(lo), "f"(hi));
    return r;
}
__device__ __forceinline__ void unpack2(ull v, float& lo, float& hi) {
    asm("mov.b64 {%0, %1}, %2;" : "=f"(lo), "=f"(hi) : "l"(v));
}
__device__ __forceinline__ ull fma2(ull a, ull b, ull c) {
    ull d;
    asm("fma.rn.f32x2 %0, %1, %2, %3;" : "=l"(d) : "l"(a), "l"(b), "l"(c));
    return d;
}

// smem (floats):
//   [0, 512)       sxc : compacted scaled x (+ sentinels)
//   [512, 1024)    sidx: compacted t index (int)
//   [1024, 9216)   skyc: float2[MM][CH] chunk of (k,y); overlaid as scr
//   [9216, 9220)   swsum[4]
// total 9220 floats = 36.9 KB.
// block: 128 thr = 32 p-lanes x 4 t-quarters; 1 p/thread, all 16 m.
// grid (19, 32) = 608 blocks -> all resident in one wave (cap 5/SM).

template<bool EQ>
__device__ __forceinline__ void chunk_mma(
    const float* sxc, const float2* skyc, int c0, int cend, int tq,
    float v, float r0, float r1, ull* __restrict__ acc)
{
    for (int jj = c0 + 2 * tq; jj < cend; jj += 8) {
        float2 xv = *(const float2*)(sxc + jj);        // LDS.64 broadcast
        float d0 = v - xv.x, d1 = v - xv.y;
        float e0 = d0 * (-d0), e1 = d1 * (-d1);

        ull wp0, wp1;
        if (EQ) {
            float w0 = ex2(e0), w1 = ex2(e1);
            wp0 = pack2(w0, w0);
            wp1 = pack2(w1, w1);
        } else {
            wp0 = pack2(ex2(e0 * r0), ex2(e0 * r1));
            wp1 = pack2(ex2(e1 * r0), ex2(e1 * r1));
        }

        const int jl = jj - c0;
        #pragma unroll
        for (int m = 0; m < MM; m++) {
            ulonglong2 q = *(const ulonglong2*)(skyc + m * CH + jl); // LDS.128
            acc[m] = fma2(q.y, wp1, fma2(q.x, wp0, acc[m]));
        }
    }
}

__global__ __launch_bounds__(128, 5) void func_repr_kernel(
    const float* __restrict__ y, const float* __restrict__ x,
    const int*   __restrict__ mask, const float* __restrict__ sigma,
    float* __restrict__ out)
{
    extern __shared__ float sm[];
    float*  sxc   = sm;
    int*    sidx  = (int*)(sm + 512);
    float2* skyc  = (float2*)(sm + 1024);
    int*    swsum = (int*)(sm + 9216);

    const int b    = blockIdx.y;
    const int tid  = threadIdx.x;
    const int lane = tid & 31;
    const int wrp  = tid >> 5;
    const int pl   = lane;
    const int tq   = wrp;

    const float s0 = sigma[0], s1 = sigma[1];
    const float LOG2E = 1.4426950408889634f;
    const float smax  = fmaxf(s0, s1);
    const float rcmin = sqrtf(0.5f * LOG2E) / smax;     // sqrt(c_min)
    const float r0 = (smax / s0) * (smax / s0);
    const float r1 = (smax / s1) * (smax / s1);

    const int   pfirst = blockIdx.x * PW;
    const float gA = fmaf((float)pfirst,            50.0f / 599.0f, -1.0f);
    const float gZ = fmaf((float)(pfirst + PW - 1), 50.0f / 599.0f, -1.0f);
    const float vlo = rcmin * gA - 6.7f;   // 6.7^2=44.9 -> dropped weight <= 3e-14
    const float vhi = rcmin * gZ + 6.7f;

    // ---- deterministic compaction of x into [vlo, vhi] ----
    float4 xv4 = ((const float4*)(x + (size_t)b * TT))[tid];  // t = 4*tid..+3
    float vv[4] = { xv4.x * rcmin, xv4.y * rcmin, xv4.z * rcmin, xv4.w * rcmin };
    int pass = 0, cnt = 0;
    #pragma unroll
    for (int k = 0; k < 4; k++) {
        bool in = (vv[k] >= vlo) & (vv[k] <= vhi);
        pass |= (int)in << k;
        cnt  += (int)in;
    }
    int incl = cnt;
    #pragma unroll
    for (int o = 1; o < 32; o <<= 1) {
        int n = __shfl_up_sync(0xFFFFFFFFu, incl, o);
        if (lane >= o) incl += n;
    }
    if (lane == 31) swsum[wrp] = incl;
    __syncthreads();

    int w0 = swsum[0], w1 = swsum[1], w2 = swsum[2], w3 = swsum[3];
    int woff = (wrp > 0 ? w0 : 0) + (wrp > 1 ? w1 : 0) + (wrp > 2 ? w2 : 0);
    const int K  = w0 + w1 + w2 + w3;
    const int Kp = (K + 7) & ~7;

    {
        int pos = woff + incl - cnt;
        #pragma unroll
        for (int k = 0; k < 4; k++) {
            if ((pass >> k) & 1) {
                sxc[pos]  = vv[k];
                sidx[pos] = tid * 4 + k;
                pos++;
            }
        }
    }
    if (tid < Kp - K) sxc[K + tid] = 1.0e9f;   // sentinel -> weight 0
    __syncthreads();

    const int p = pfirst + pl;
    const float v = rcmin * fmaf((float)p, 50.0f / 599.0f, -1.0f);

    ull acc[MM];
    #pragma unroll
    for (int m = 0; m < MM; m++) acc[m] = 0ULL;

    const float* yb = y    + (size_t)b * MM * TT;
    const int*   mb = mask + (size_t)b * MM * TT;

    // ---- chunked gather + MMA (typical K<=256: one iteration) ----
    for (int c0 = 0; c0 < Kp; c0 += CH) {
        const int cend = min(c0 + CH, Kp);

        // coalesced gather: warp takes 4 m-rows, lanes take consecutive j
        #pragma unroll
        for (int m = wrp; m < MM; m += 4) {
            const int*   mrow = mb + m * TT;
            const float* yrow = yb + m * TT;
            for (int j = c0 + lane; j < cend; j += 32) {
                float2 kv;
                if (j < K) {
                    int t = sidx[j];
                    kv = make_float2((float)__ldg(mrow + t), __ldg(yrow + t));
                } else {
                    kv = make_float2(0.f, 0.f);
                }
                skyc[m * CH + (j - c0)] = kv;
            }
        }
        __syncthreads();

        if (s0 == s1)
            chunk_mma<true >(sxc, skyc, c0, cend, tq, v, r0, r1, acc);
        else
            chunk_mma<false>(sxc, skyc, c0, cend, tq, v, r0, r1, acc);
        __syncthreads();   // before next chunk / scr overlay
    }

    // ---- cross-quarter reduction (scratch overlays skyc) ----
    float* scr = sm + 1024;           // 3 * 32 * 33 = 3168 <= 8192 floats
    if (tq > 0) {
        float* s = scr + ((tq - 1) * 32 + pl) * 33;
        #pragma unroll
        for (int m = 0; m < MM; m++) {
            float lo, hi;
            unpack2(acc[m], lo, hi);
            s[2 * m]     = lo;
            s[2 * m + 1] = hi;
        }
    }
    __syncthreads();

    if (tq == 0 && p < PP) {
        const float* q1 = scr + (0 * 32 + pl) * 33;
        const float* q2 = scr + (1 * 32 + pl) * 33;
        const float* q3 = scr + (2 * 32 + pl) * 33;
        float4* op = (float4*)(out + ((size_t)b * PP + p) * (2 * MM));
        #pragma unroll
        for (int m = 0; m < MM; m += 2) {
            float dA, cA, dB, cB;
            unpack2(acc[m],     dA, cA);
            unpack2(acc[m + 1], dB, cB);
            dA += q1[2*m]   + q2[2*m]   + q3[2*m];
            cA += q1[2*m+1] + q2[2*m+1] + q3[2*m+1];
            dB += q1[2*m+2] + q2[2*m+2] + q3[2*m+2];
            cB += q1[2*m+3] + q2[2*m+3] + q3[2*m+3];
            op[m >> 1] = make_float4(dA, __fdividef(cA, dA + 1e-8f),
                                     dB, __fdividef(cB, dB + 1e-8f));
        }
    }
}

extern "C" void kernel_launch(void* const* d_in, const int* in_sizes, int n_in,
                              void* d_out, int out_size) {
    const float* y     = (const float*)d_in[0];
    const float* x     = (const float*)d_in[1];
    const int*   mask  = (const int*)  d_in[2];
    const float* sigma = (const float*)d_in[3];
    float*       out   = (float*)d_out;

    const size_t smem = 9220 * sizeof(float);   // 36.9 KB
    cudaFuncSetAttribute(func_repr_kernel,
                         cudaFuncAttributeMaxDynamicSharedMemorySize, (int)smem);

    dim3 grid(NPT, BB);
    func_repr_kernel<<<grid, 128, smem>>>(y, x, mask, sigma, out);
}

// round 10
// speedup vs baseline: 1.0727x; 1.0519x over previous
#include <cuda_runtime.h>
#include <cuda_bf16.h>

#define TT 512
#define MM 16
#define MH 8
#define PP 600
#define BB 32
#define PW 32
#define NPT 19
#define UNITS (BB * NPT * 2)            // 1216 warp units
#define WPB 9
#define NBLK ((UNITS + WPB - 1) / WPB)  // 136 blocks <= 148 SMs
#define KMAX 128                        // sky chunk length

typedef unsigned long long ull;

__device__ __forceinline__ float ex2(float v) {
    float r;
    asm("ex2.approx.ftz.f32 %0, %1;" : "=f"(r) : "f"(v));
    return r;
}
__device__ __forceinline__ ull pack2(float lo, float hi) {
    ull r;
    asm("mov.b64 %0, {%1, %2};" : "=l"(r) : "f"(lo), "f"(hi));
    return r;
}
__device__ __forceinline__ void unpack2(ull v, float& lo, float& hi) {
    asm("mov.b64 {%0, %1}, %2;" : "=f"(lo), "=f"(hi) : "l"(v));
}
__device__ __forceinline__ ull fma2(ull a, ull b, ull c) {
    ull d;
    asm("fma.rn.f32x2 %0, %1, %2, %3;" : "=l"(d) : "l"(a), "l"(b), "l"(c));
    return d;
}

// Per-warp private smem slice (floats):
//   sxc[512] scaled compacted x | sidx[512] t-index | sky[MH][KMAX] float2
#define SLICE (512 + 512 + MH * KMAX * 2)   // 3072 floats = 12 KB
// Block = 9 warps -> 108 KB dynamic smem. No __syncthreads anywhere.

template<bool EQ>
__device__ __forceinline__ void chunk_mma(
    const float* sxc, const float2* sky, int c0, int cend,
    float v, float r0, float r1, ull* __restrict__ acc)
{
    for (int jj = c0; jj < cend; jj += 2) {
        float2 xv = *(const float2*)(sxc + jj);        // LDS.64 broadcast
        float d0 = v - xv.x, d1 = v - xv.y;
        float e0 = d0 * (-d0), e1 = d1 * (-d1);

        ull wp0, wp1;
        if (EQ) {
            float w0 = ex2(e0), w1 = ex2(e1);
            wp0 = pack2(w0, w0);
            wp1 = pack2(w1, w1);
        } else {
            wp0 = pack2(ex2(e0 * r0), ex2(e0 * r1));
            wp1 = pack2(ex2(e1 * r0), ex2(e1 * r1));
        }

        const int jl = jj - c0;
        #pragma unroll
        for (int m = 0; m < MH; m++) {
            ulonglong2 q = *(const ulonglong2*)(sky + m * KMAX + jl); // LDS.128
            acc[m] = fma2(q.y, wp1, fma2(q.x, wp0, acc[m]));
        }
    }
}

__global__ __launch_bounds__(WPB * 32) void func_repr_kernel(
    const float* __restrict__ y, const float* __restrict__ x,
    const int*   __restrict__ mask, const float* __restrict__ sigma,
    float* __restrict__ out)
{
    extern __shared__ float sm[];
    const int tid  = threadIdx.x;
    const int lane = tid & 31;
    const int w    = tid >> 5;

    const int unit = blockIdx.x * WPB + w;
    if (unit >= UNITS) return;                 // whole warp exits; no barriers

    const int half = unit & 1;
    const int bt   = unit >> 1;
    const int b    = bt / NPT;
    const int tile = bt % NPT;

    float*  sxc  = sm + w * SLICE;
    int*    sidx = (int*)(sxc + 512);
    float2* sky  = (float2*)(sxc + 1024);

    const float s0 = sigma[0], s1 = sigma[1];
    const float LOG2E = 1.4426950408889634f;
    const float smax  = fmaxf(s0, s1);
    const float rcmin = sqrtf(0.5f * LOG2E) / smax;     // sqrt(c_min)
    const float r0 = (smax / s0) * (smax / s0);
    const float r1 = (smax / s1) * (smax / s1);

    const int   pfirst = tile * PW;
    const float gA = fmaf((float)pfirst,            50.0f / 599.0f, -1.0f);
    const float gZ = fmaf((float)(pfirst + PW - 1), 50.0f / 599.0f, -1.0f);
    const float vlo = rcmin * gA - 6.7f;   // dropped weight <= 2^-44.9
    const float vhi = rcmin * gZ + 6.7f;

    // ---- warp-private load of x + ballot compaction (ascending t) ----
    const float* xr = x + (size_t)b * TT;
    float xs[16];
    #pragma unroll
    for (int r = 0; r < 16; r++) xs[r] = xr[r * 32 + lane] * rcmin;

    const unsigned lmlt = (1u << lane) - 1u;
    int base = 0;
    #pragma unroll
    for (int r = 0; r < 16; r++) {
        bool in = (xs[r] >= vlo) & (xs[r] <= vhi);
        unsigned msk = __ballot_sync(0xFFFFFFFFu, in);
        if (in) {
            int pos = base + __popc(msk & lmlt);
            sxc[pos]  = xs[r];
            sidx[pos] = r * 32 + lane;
        }
        base += __popc(msk);
    }
    const int K  = base;
    const int Kp = (K + 1) & ~1;
    if (lane == 0 && Kp > K) sxc[K] = 1.0e9f;    // sentinel -> weight 0
    __syncwarp();

    const int   p = pfirst + lane;
    const float v = rcmin * fmaf((float)p, 50.0f / 599.0f, -1.0f);

    ull acc[MH];
    #pragma unroll
    for (int m = 0; m < MH; m++) acc[m] = 0ULL;

    const float* yb = y    + ((size_t)b * MM + half * MH) * TT;
    const int*   mb = mask + ((size_t)b * MM + half * MH) * TT;

    // ---- chunked warp-private gather + mma (typical K<=128: one chunk) ----
    for (int c0 = 0; c0 < Kp; c0 += KMAX) {
        const int cend = min(c0 + KMAX, Kp);

        for (int j = c0 + lane; j < cend; j += 32) {
            if (j < K) {
                int t = sidx[j];
                #pragma unroll
                for (int m = 0; m < MH; m++)
                    sky[m * KMAX + (j - c0)] =
                        make_float2((float)__ldg(mb + m * TT + t),
                                    __ldg(yb + m * TT + t));
            } else {
                #pragma unroll
                for (int m = 0; m < MH; m++)
                    sky[m * KMAX + (j - c0)] = make_float2(0.f, 0.f);
            }
        }
        __syncwarp();

        if (s0 == s1)
            chunk_mma<true >(sxc, sky, c0, cend, v, r0, r1, acc);
        else
            chunk_mma<false>(sxc, sky, c0, cend, v, r0, r1, acc);
        __syncwarp();
    }

    // ---- epilogue: each lane owns p completely; no reduction ----
    if (p < PP) {
        float4* op = (float4*)(out + ((size_t)b * PP + p) * (2 * MM) + half * 2 * MH);
        #pragma unroll
        for (int m = 0; m < MH; m += 2) {
            float dA, cA, dB, cB;
            unpack2(acc[m],     dA, cA);
            unpack2(acc[m + 1], dB, cB);
            op[m >> 1] = make_float4(dA, __fdividef(cA, dA + 1e-8f),
                                     dB, __fdividef(cB, dB + 1e-8f));
        }
    }
}

extern "C" void kernel_launch(void* const* d_in, const int* in_sizes, int n_in,
                              void* d_out, int out_size) {
    const float* y     = (const float*)d_in[0];
    const float* x     = (const float*)d_in[1];
    const int*   mask  = (const int*)  d_in[2];
    const float* sigma = (const float*)d_in[3];
    float*       out   = (float*)d_out;

    const size_t smem = (size_t)WPB * SLICE * sizeof(float);   // 108 KB
    cudaFuncSetAttribute(func_repr_kernel,
                         cudaFuncAttributeMaxDynamicSharedMemorySize, (int)smem);

    func_repr_kernel<<<NBLK, WPB * 32, smem>>>(y, x, mask, sigma, out);
}

// round 11
// speedup vs baseline: 1.1766x; 1.0969x over previous
#include <cuda_runtime.h>
#include <cuda_bf16.h>

#define TT 512
#define MM 16
#define MQ 4            // m rows per warp unit
#define PP 600
#define BB 32
#define PW 32
#define NPT 19
#define UNITS (BB * NPT * 4)            // 2432 warp units
#define WPB 9
#define NBLK ((UNITS + WPB - 1) / WPB)  // 271 blocks -> <=2 per SM
#define TH 256          // t-half length
#define CH 64           // gather/mma chunk

typedef unsigned long long ull;

__device__ __forceinline__ float ex2(float v) {
    float r;
    asm("ex2.approx.ftz.f32 %0, %1;" : "=f"(r) : "f"(v));
    return r;
}
__device__ __forceinline__ ull pack2(float lo, float hi) {
    ull r;
    asm("mov.b64 %0, {%1, %2};" : "=l"(r) : "f"(lo), "f"(hi));
    return r;
}
__device__ __forceinline__ void unpack2(ull v, float& lo, float& hi) {
    asm("mov.b64 {%0, %1}, %2;" : "=f"(lo), "=f"(hi) : "l"(v));
}
__device__ __forceinline__ ull fma2(ull a, ull b, ull c) {
    ull d;
    asm("fma.rn.f32x2 %0, %1, %2, %3;" : "=l"(d) : "l"(a), "l"(b), "l"(c));
    return d;
}

// Per-warp smem slice (floats): sxc[256] | sidx[256] (int) | sky[MQ][CH] float2
#define SLICE (TH + TH + MQ * CH * 2)   // 1024 floats = 4 KB
// Block = 9 warps -> 36 KB. No __syncthreads anywhere; warps fully autonomous.

template<bool EQ>
__device__ __forceinline__ void chunk_mma(
    const float* sxc, const float2* sky, int c0, int cend,
    float v, float r0, float r1, ull* __restrict__ acc)
{
    for (int jj = c0; jj < cend; jj += 2) {
        float2 xv = *(const float2*)(sxc + jj);        // LDS.64 broadcast
        float d0 = v - xv.x, d1 = v - xv.y;
        float e0 = d0 * (-d0), e1 = d1 * (-d1);

        ull wp0, wp1;
        if (EQ) {
            float w0 = ex2(e0), w1 = ex2(e1);
            wp0 = pack2(w0, w0);
            wp1 = pack2(w1, w1);
        } else {
            wp0 = pack2(ex2(e0 * r0), ex2(e0 * r1));
            wp1 = pack2(ex2(e1 * r0), ex2(e1 * r1));
        }

        const int jl = jj - c0;
        #pragma unroll
        for (int m = 0; m < MQ; m++) {
            ulonglong2 q = *(const ulonglong2*)(sky + m * CH + jl); // LDS.128
            acc[m] = fma2(q.y, wp1, fma2(q.x, wp0, acc[m]));
        }
    }
}

__global__ __launch_bounds__(WPB * 32) void func_repr_kernel(
    const float* __restrict__ y, const float* __restrict__ x,
    const int*   __restrict__ mask, const float* __restrict__ sigma,
    float* __restrict__ out)
{
    extern __shared__ float sm[];
    const int tid  = threadIdx.x;
    const int lane = tid & 31;
    const int w    = tid >> 5;

    const int unit = blockIdx.x * WPB + w;
    if (unit >= UNITS) return;                 // warp-level exit; no barriers

    const int quarter = unit & 3;
    const int bt      = unit >> 2;
    const int b       = bt / NPT;
    const int tile    = bt % NPT;

    float*  sxc  = sm + w * SLICE;
    int*    sidx = (int*)(sxc + TH);
    float2* sky  = (float2*)(sxc + 2 * TH);

    const float s0 = sigma[0], s1 = sigma[1];
    const float LOG2E = 1.4426950408889634f;
    const float smax  = fmaxf(s0, s1);
    const float rcmin = sqrtf(0.5f * LOG2E) / smax;     // sqrt(c_min)
    const float r0 = (smax / s0) * (smax / s0);
    const float r1 = (smax / s1) * (smax / s1);

    const int   pfirst = tile * PW;
    const float gA = fmaf((float)pfirst,            50.0f / 599.0f, -1.0f);
    const float gZ = fmaf((float)(pfirst + PW - 1), 50.0f / 599.0f, -1.0f);
    const float vlo = rcmin * gA - 6.7f;   // dropped weight <= 2^-44.9
    const float vhi = rcmin * gZ + 6.7f;

    const int   p = pfirst + lane;
    const float v = rcmin * fmaf((float)p, 50.0f / 599.0f, -1.0f);

    ull acc[MQ];
    #pragma unroll
    for (int m = 0; m < MQ; m++) acc[m] = 0ULL;

    const float* xr = x + (size_t)b * TT;
    const float* yb = y    + ((size_t)b * MM + quarter * MQ) * TT;
    const int*   mb = mask + ((size_t)b * MM + quarter * MQ) * TT;
    const unsigned lmlt = (1u << lane) - 1u;
    const bool eq = (s0 == s1);

    #pragma unroll
    for (int half = 0; half < 2; half++) {
        const int t0 = half * TH;

        // ---- warp-private ballot compaction of this t-half ----
        int base = 0;
        #pragma unroll
        for (int r = 0; r < TH / 32; r++) {
            float xs = xr[t0 + r * 32 + lane] * rcmin;
            bool in = (xs >= vlo) & (xs <= vhi);
            unsigned msk = __ballot_sync(0xFFFFFFFFu, in);
            if (in) {
                int pos = base + __popc(msk & lmlt);
                sxc[pos]  = xs;
                sidx[pos] = t0 + r * 32 + lane;
            }
            base += __popc(msk);
        }
        const int K = base;
        int Kp = K;
        if (K & 1) {
            if (lane == 0 && K < TH) sxc[K] = 1.0e9f;  // sentinel -> weight 0
            Kp = K + 1;
        }
        __syncwarp();

        // ---- chunked private gather + mma (typical K~28: one chunk) ----
        for (int c0 = 0; c0 < Kp; c0 += CH) {
            const int cend = min(c0 + CH, Kp);

            for (int j = c0 + lane; j < cend; j += 32) {
                if (j < K) {
                    int t = sidx[j];
                    #pragma unroll
                    for (int m = 0; m < MQ; m++)
                        sky[m * CH + (j - c0)] =
                            make_float2((float)__ldg(mb + m * TT + t),
                                        __ldg(yb + m * TT + t));
                } else {
                    #pragma unroll
                    for (int m = 0; m < MQ; m++)
                        sky[m * CH + (j - c0)] = make_float2(0.f, 0.f);
                }
            }
            __syncwarp();

            if (eq)
                chunk_mma<true >(sxc, sky, c0, cend, v, r0, r1, acc);
            else
                chunk_mma<false>(sxc, sky, c0, cend, v, r0, r1, acc);
            __syncwarp();
        }
    }

    // ---- epilogue: lane owns p completely; no reduction ----
    if (p < PP) {
        float4* op = (float4*)(out + ((size_t)b * PP + p) * (2 * MM)
                               + quarter * 2 * MQ);
        #pragma unroll
        for (int m = 0; m < MQ; m += 2) {
            float dA, cA, dB, cB;
            unpack2(acc[m],     dA, cA);
            unpack2(acc[m + 1], dB, cB);
            op[m >> 1] = make_float4(dA, __fdividef(cA, dA + 1e-8f),
                                     dB, __fdividef(cB, dB + 1e-8f));
        }
    }
}

extern "C" void kernel_launch(void* const* d_in, const int* in_sizes, int n_in,
                              void* d_out, int out_size) {
    const float* y     = (const float*)d_in[0];
    const float* x     = (const float*)d_in[1];
    const int*   mask  = (const int*)  d_in[2];
    const float* sigma = (const float*)d_in[3];
    float*       out   = (float*)d_out;

    const size_t smem = (size_t)WPB * SLICE * sizeof(float);   // 36 KB
    cudaFuncSetAttribute(func_repr_kernel,
                         cudaFuncAttributeMaxDynamicSharedMemorySize, (int)smem);

    func_repr_kernel<<<NBLK, WPB * 32, smem>>>(y, x, mask, sigma, out);
}